// round 10
// baseline (speedup 1.0000x reference)
#include <cuda_runtime.h>
#include <cuda_fp16.h>
#include <stdint.h>

#define HASH_MASK ((1u << 19) - 1u)
#define RES 128.0f
#define P1 2654435761u
#define P2 805459861u

#define GD 128
// octo fp16 grid, x-INNERMOST layout: entry(fy,fz,fx) = 8 packed half2 words
// [ v(fx,y,z), v(fx,y,z+1), v(fx,y+1,z), v(fx,y+1,z+1),
//   v(fx+1,...) same four ].  32B per entry -> one L2 sector per point. 67 MB.
// idx = ((fy*128 + fz)*128 + fx)
__device__ __align__(32) uint32_t g_octo[GD * GD * GD * 8];

__device__ __forceinline__ float2 up2(uint32_t u) {
    __half2 h = *reinterpret_cast<__half2*>(&u);
    return __half22float2(h);
}

__device__ __forceinline__ void ld_octo(const uint32_t* p, uint32_t r[8]) {
    asm("ld.global.v8.b32 {%0,%1,%2,%3,%4,%5,%6,%7}, [%8];"
        : "=r"(r[0]), "=r"(r[1]), "=r"(r[2]), "=r"(r[3]),
          "=r"(r[4]), "=r"(r[5]), "=r"(r[6]), "=r"(r[7])
        : "l"(p));
}

__device__ __forceinline__ uint32_t smem_u32(const void* p) {
    uint32_t a;
    asm("{ .reg .u64 t; cvta.to.shared.u64 t, %1; cvt.u32.u64 %0, t; }"
        : "=r"(a) : "l"(p));
    return a;
}

// ---------------- Pass 1: densify, TMA bulk stores ----------------
// Block per 4x8 (y,z) tile covering all ix. Gathers use XOR-window coalescing
// (hash XOR-linear in ix). Output assembled in smem, written with 4x 32KB
// cp.async.bulk — no per-sector L1 store wavefronts.
#define TY 4
#define TZ 8
#define NROWS ((TY + 1) * (TZ + 1))   // 45 hash rows
#define SROW 132                      // padded staging stride (words)
#define STAGE_WORDS (NROWS * SROW)    // 5940
#define ABUF_WORDS (TY * TZ * 128 * 8) // 32768 words = 128KB
#define SMEM_BYTES ((STAGE_WORDS + ABUF_WORDS) * 4)

__global__ void __launch_bounds__(256) densify_kernel(const float2* __restrict__ ht)
{
    extern __shared__ uint32_t dyn[];
    uint32_t* s    = dyn;                 // staging: [45][SROW]
    uint32_t* abuf = dyn + STAGE_WORDS;   // assembly: [(yl*8+zl)*128+fx]*8+k

    int by = (blockIdx.x >> 4) * TY;
    int bz = (blockIdx.x & 15) * TZ;

    int tid = threadIdx.x;
    int warp = tid >> 5;
    int lane = tid & 31;

    // Gather phase: rows (y,z) halo, lanes sweep ix (XOR windows).
    for (int r = warp; r < NROWS; r += 8) {
        int yl = r / (TZ + 1);
        int zl = r - yl * (TZ + 1);
        uint32_t base = ((uint32_t)(by + yl) * P1) ^ ((uint32_t)(bz + zl) * P2);
        for (int ix = lane; ix < 129; ix += 32) {
            float2 v = __ldg(&ht[(base ^ (uint32_t)ix) & HASH_MASK]);
            __half2 hh = __floats2half2_rn(v.x, v.y);
            s[r * SROW + ix] = *reinterpret_cast<uint32_t*>(&hh);
        }
    }
    __syncthreads();

    // Assembly phase: build octo words in gmem order (conflict-light STS.32).
    for (int w = tid; w < ABUF_WORDS; w += 256) {
        int k  = w & 7;
        int fx = (w >> 3) & 127;
        int zl = (w >> 10) & 7;
        int yl = w >> 13;
        int dy = (k >> 1) & 1;
        int dz = k & 1;
        int xo = k >> 2;
        abuf[w] = s[((yl + dy) * (TZ + 1) + (zl + dz)) * SROW + fx + xo];
    }
    __syncthreads();

    // TMA bulk store phase: 4 x 32KB contiguous copies (one per y row-group).
    asm volatile("fence.proxy.async.shared::cta;" ::: "memory");
    if (tid == 0) {
        for (int yl = 0; yl < TY; yl++) {
            uint32_t* dst = &g_octo[(((by + yl) * GD + bz) * GD) * 8];
            uint32_t src = smem_u32(&abuf[yl * (TZ * 128 * 8)]);
            asm volatile(
                "cp.async.bulk.global.shared::cta.bulk_group [%0], [%1], %2;"
                :: "l"(dst), "r"(src), "r"(TZ * 128 * 8 * 4) : "memory");
        }
        asm volatile("cp.async.bulk.commit_group;" ::: "memory");
        asm volatile("cp.async.bulk.wait_group.read 0;" ::: "memory");
    }
    __syncthreads();  // keep smem alive until TMA reads complete
}

// ---------------- Pass 2: trilinear interp, 2 pts/thread, 1 LDG.256/pt ----------------
__device__ __forceinline__ void lerp8(
    const uint32_t w[8], float dx, float dy, float dz, float& oa, float& ob)
{
    float2 v000 = up2(w[0]), v001 = up2(w[1]), v010 = up2(w[2]), v011 = up2(w[3]);
    float2 v100 = up2(w[4]), v101 = up2(w[5]), v110 = up2(w[6]), v111 = up2(w[7]);

    float omx = 1.0f - dx, omy = 1.0f - dy, omz = 1.0f - dz;

    float c00a = v000.x * omx + v100.x * dx;
    float c00b = v000.y * omx + v100.y * dx;
    float c01a = v001.x * omx + v101.x * dx;
    float c01b = v001.y * omx + v101.y * dx;
    float c10a = v010.x * omx + v110.x * dx;
    float c10b = v010.y * omx + v110.y * dx;
    float c11a = v011.x * omx + v111.x * dx;
    float c11b = v011.y * omx + v111.y * dx;

    float c0a = c00a * omy + c10a * dy;
    float c0b = c00b * omy + c10b * dy;
    float c1a = c01a * omy + c11a * dy;
    float c1b = c01b * omy + c11b * dy;

    oa = c0a * omz + c1a * dz;
    ob = c0b * omz + c1b * dz;
}

__global__ void __launch_bounds__(256) ngp_interp_kernel(
    const float* __restrict__ x,
    float2* __restrict__ out,
    int n)
{
    int t = blockIdx.x * blockDim.x + threadIdx.x;
    int i0 = t * 2;
    if (i0 >= n) return;

    const float2* __restrict__ x2 = (const float2*)x;
    float2 a = __ldcs(&x2[3 * t + 0]);
    float2 b = __ldcs(&x2[3 * t + 1]);
    float2 c = __ldcs(&x2[3 * t + 2]);

    float sx0 = a.x * RES, sy0 = a.y * RES, sz0 = b.x * RES;
    float fx0 = floorf(sx0), fy0 = floorf(sy0), fz0 = floorf(sz0);
    int b0 = ((int)fy0 * GD + (int)fz0) * GD + (int)fx0;   // x-innermost

    float sx1 = b.y * RES, sy1 = c.x * RES, sz1 = c.y * RES;
    float fx1 = floorf(sx1), fy1 = floorf(sy1), fz1 = floorf(sz1);
    int b1 = ((int)fy1 * GD + (int)fz1) * GD + (int)fx1;

    uint32_t w0[8], w1[8];
    ld_octo(&g_octo[b0 * 8], w0);
    ld_octo(&g_octo[b1 * 8], w1);

    float o0a, o0b, o1a, o1b;
    lerp8(w0, sx0 - fx0, sy0 - fy0, sz0 - fz0, o0a, o0b);
    lerp8(w1, sx1 - fx1, sy1 - fy1, sz1 - fz1, o1a, o1b);

    if (i0 + 1 < n) {
        float4* __restrict__ out4 = (float4*)out;
        __stcs(&out4[t], make_float4(o0a, o0b, o1a, o1b));
    } else {
        __stcs(&out[i0], make_float2(o0a, o0b));
    }
}

extern "C" void kernel_launch(void* const* d_in, const int* in_sizes, int n_in,
                              void* d_out, int out_size) {
    const float* x = (const float*)d_in[0];
    const float2* ht = (const float2*)d_in[1];
    float2* out = (float2*)d_out;
    int n = in_sizes[0] / 3;

    static int smem_set = 0;
    if (!smem_set) {
        cudaFuncSetAttribute(densify_kernel,
                             cudaFuncAttributeMaxDynamicSharedMemorySize,
                             SMEM_BYTES);
        smem_set = 1;
    }

    densify_kernel<<<512, 256, SMEM_BYTES>>>(ht);

    int threads = 256;
    int pts_per_block = threads * 2;
    int blocks = (n + pts_per_block - 1) / pts_per_block;
    ngp_interp_kernel<<<blocks, threads>>>(x, out, n);
}

// round 11
// speedup vs baseline: 1.8995x; 1.8995x over previous
#include <cuda_runtime.h>
#include <cuda_fp16.h>
#include <stdint.h>

#define HASH_MASK ((1u << 19) - 1u)
#define RES 128.0f
#define P1 2654435761u
#define P2 805459861u

#define GD 128
// octo fp16 grid: entry(fx,fy,fz) = 8 packed half2 words:
// [ quad(fx):  v(y,z), v(y,z+1), v(y+1,z), v(y+1,z+1);  quad(fx+1): same ]
// 32 B per entry, 32B-aligned -> one L2 sector per point. 67 MB.
// idx = ((fx*GD + fy)*GD + fz)
__device__ __align__(32) uint32_t g_octo[GD * GD * GD * 8];

__device__ __forceinline__ float2 up2(uint32_t u) {
    __half2 h = *reinterpret_cast<__half2*>(&u);
    return __half22float2(h);
}

__device__ __forceinline__ void ld_octo(const uint32_t* p, uint32_t r[8]) {
    asm("ld.global.v8.b32 {%0,%1,%2,%3,%4,%5,%6,%7}, [%8];"
        : "=r"(r[0]), "=r"(r[1]), "=r"(r[2]), "=r"(r[3]),
          "=r"(r[4]), "=r"(r[5]), "=r"(r[6]), "=r"(r[7])
        : "l"(p));
}

__device__ __forceinline__ void st_octo(uint32_t* p, uint32_t w0, uint32_t w1,
                                        uint32_t w2, uint32_t w3, uint32_t w4,
                                        uint32_t w5, uint32_t w6, uint32_t w7) {
    asm volatile("st.global.v8.b32 [%0], {%1,%2,%3,%4,%5,%6,%7,%8};"
                 :: "l"(p), "r"(w0), "r"(w1), "r"(w2), "r"(w3),
                    "r"(w4), "r"(w5), "r"(w6), "r"(w7) : "memory");
}

// ---------------- Pass 1: densify (XOR-window gathers, MLP-unrolled) ----------------
#define TY 4
#define TZ 8
#define NROWS ((TY + 1) * (TZ + 1))   // 45
#define SROW 133                      // padded stride vs bank conflicts

__global__ void __launch_bounds__(256) densify_kernel(const float2* __restrict__ ht)
{
    int by = (blockIdx.x >> 4) * TY;   // 32 y-tiles
    int bz = (blockIdx.x & 15) * TZ;   // 16 z-tiles

    __shared__ uint32_t s[NROWS * SROW];

    int tid = threadIdx.x;
    int warp = tid >> 5;
    int lane = tid & 31;

    // Gather phase: per row, all 4 XOR-window loads (+ straggler) issued
    // back-to-back into registers before any STS -> MLP 4-5 per warp.
    for (int r = warp; r < NROWS; r += 8) {
        int yl = r / (TZ + 1);
        int zl = r - yl * (TZ + 1);
        uint32_t base = ((uint32_t)(by + yl) * P1) ^ ((uint32_t)(bz + zl) * P2);

        float2 v0 = __ldg(&ht[(base ^ (uint32_t)(lane      )) & HASH_MASK]);
        float2 v1 = __ldg(&ht[(base ^ (uint32_t)(lane + 32 )) & HASH_MASK]);
        float2 v2 = __ldg(&ht[(base ^ (uint32_t)(lane + 64 )) & HASH_MASK]);
        float2 v3 = __ldg(&ht[(base ^ (uint32_t)(lane + 96 )) & HASH_MASK]);
        float2 v4 = __ldg(&ht[(base ^ 128u) & HASH_MASK]);   // all lanes, broadcast

        __half2 h0 = __floats2half2_rn(v0.x, v0.y);
        __half2 h1 = __floats2half2_rn(v1.x, v1.y);
        __half2 h2 = __floats2half2_rn(v2.x, v2.y);
        __half2 h3 = __floats2half2_rn(v3.x, v3.y);
        uint32_t* row = &s[r * SROW];
        row[lane      ] = *reinterpret_cast<uint32_t*>(&h0);
        row[lane + 32 ] = *reinterpret_cast<uint32_t*>(&h1);
        row[lane + 64 ] = *reinterpret_cast<uint32_t*>(&h2);
        row[lane + 96 ] = *reinterpret_cast<uint32_t*>(&h3);
        if (lane == 0) {
            __half2 h4 = __floats2half2_rn(v4.x, v4.y);
            row[128] = *reinterpret_cast<uint32_t*>(&h4);
        }
    }
    __syncthreads();

    // Store phase: 32B octo entries; lanes sweep (yl,zl) -> coalesced v8 stores.
    for (int e = tid; e < GD * TY * TZ; e += 256) {
        int ix = e >> 5;
        int q  = e & 31;
        int yl = q >> 3;
        int zl = q & 7;
        int r = yl * (TZ + 1) + zl;
        uint32_t w0 = s[r * SROW + ix];
        uint32_t w1 = s[(r + 1) * SROW + ix];
        uint32_t w2 = s[(r + TZ + 1) * SROW + ix];
        uint32_t w3 = s[(r + TZ + 2) * SROW + ix];
        uint32_t w4 = s[r * SROW + ix + 1];
        uint32_t w5 = s[(r + 1) * SROW + ix + 1];
        uint32_t w6 = s[(r + TZ + 1) * SROW + ix + 1];
        uint32_t w7 = s[(r + TZ + 2) * SROW + ix + 1];
        uint32_t* dst = &g_octo[(((ix * GD) + by + yl) * GD + bz + zl) * 8];
        st_octo(dst, w0, w1, w2, w3, w4, w5, w6, w7);
    }
}

// ---------------- Pass 2: trilinear interp, 2 pts/thread, 1 LDG.256/pt ----------------
__device__ __forceinline__ void lerp8(
    const uint32_t w[8], float dx, float dy, float dz, float& oa, float& ob)
{
    float2 v000 = up2(w[0]), v001 = up2(w[1]), v010 = up2(w[2]), v011 = up2(w[3]);
    float2 v100 = up2(w[4]), v101 = up2(w[5]), v110 = up2(w[6]), v111 = up2(w[7]);

    float omx = 1.0f - dx, omy = 1.0f - dy, omz = 1.0f - dz;

    float c00a = v000.x * omx + v100.x * dx;
    float c00b = v000.y * omx + v100.y * dx;
    float c01a = v001.x * omx + v101.x * dx;
    float c01b = v001.y * omx + v101.y * dx;
    float c10a = v010.x * omx + v110.x * dx;
    float c10b = v010.y * omx + v110.y * dx;
    float c11a = v011.x * omx + v111.x * dx;
    float c11b = v011.y * omx + v111.y * dx;

    float c0a = c00a * omy + c10a * dy;
    float c0b = c00b * omy + c10b * dy;
    float c1a = c01a * omy + c11a * dy;
    float c1b = c01b * omy + c11b * dy;

    oa = c0a * omz + c1a * dz;
    ob = c0b * omz + c1b * dz;
}

__global__ void __launch_bounds__(256) ngp_interp_kernel(
    const float* __restrict__ x,
    float2* __restrict__ out,
    int n)
{
    int t = blockIdx.x * blockDim.x + threadIdx.x;
    int i0 = t * 2;
    if (i0 >= n) return;

    const float2* __restrict__ x2 = (const float2*)x;
    float2 a = __ldcs(&x2[3 * t + 0]);
    float2 b = __ldcs(&x2[3 * t + 1]);
    float2 c = __ldcs(&x2[3 * t + 2]);

    float sx0 = a.x * RES, sy0 = a.y * RES, sz0 = b.x * RES;
    float fx0 = floorf(sx0), fy0 = floorf(sy0), fz0 = floorf(sz0);
    int b0 = ((int)fx0 * GD + (int)fy0) * GD + (int)fz0;

    float sx1 = b.y * RES, sy1 = c.x * RES, sz1 = c.y * RES;
    float fx1 = floorf(sx1), fy1 = floorf(sy1), fz1 = floorf(sz1);
    int b1 = ((int)fx1 * GD + (int)fy1) * GD + (int)fz1;

    uint32_t w0[8], w1[8];
    ld_octo(&g_octo[b0 * 8], w0);
    ld_octo(&g_octo[b1 * 8], w1);

    float o0a, o0b, o1a, o1b;
    lerp8(w0, sx0 - fx0, sy0 - fy0, sz0 - fz0, o0a, o0b);
    lerp8(w1, sx1 - fx1, sy1 - fy1, sz1 - fz1, o1a, o1b);

    if (i0 + 1 < n) {
        float4* __restrict__ out4 = (float4*)out;
        __stcs(&out4[t], make_float4(o0a, o0b, o1a, o1b));
    } else {
        __stcs(&out[i0], make_float2(o0a, o0b));
    }
}

extern "C" void kernel_launch(void* const* d_in, const int* in_sizes, int n_in,
                              void* d_out, int out_size) {
    const float* x = (const float*)d_in[0];
    const float2* ht = (const float2*)d_in[1];
    float2* out = (float2*)d_out;
    int n = in_sizes[0] / 3;

    densify_kernel<<<512, 256>>>(ht);

    int threads = 256;
    int pts_per_block = threads * 2;
    int blocks = (n + pts_per_block - 1) / pts_per_block;
    ngp_interp_kernel<<<blocks, threads>>>(x, out, n);
}